// round 8
// baseline (speedup 1.0000x reference)
#include <cuda_runtime.h>
#include <cuda_bf16.h>
#include <cstdint>

#define L_SEQ 2048
#define BATCH 8
#define EMB   1024
#define KDIM  1024
#define MTOT  (BATCH * L_SEQ)   // 16384

// ---- GEMM tiling: CTA 128x128, 4 warps (2x2), warp tile 64x64, BK=16 ----
#define BM 128
#define BN 128
#define BK 16
#define NCHUNK (KDIM / BK)      // 64
#define GTHREADS 128
#define NSTAGE 4

// smem rows padded to 48B (32B data + 16B pad): 20-word stride is a perfect
// bank permutation mod 32 -> conflict-free ldmatrix without swizzle.
#define RSTRIDE 48
#define A_HI 0
#define A_LO (BM * RSTRIDE)                  // 6144
#define B_HI (2 * BM * RSTRIDE)              // 12288
#define B_LO (B_HI + BN * RSTRIDE)           // 18432
#define STAGE_BYTES (B_LO + BN * RSTRIDE)    // 24576
#define SMEM_BYTES (NSTAGE * STAGE_BYTES)    // 98304

// ---------------- scratch (device globals) ----------------
__device__ __nv_bfloat16 g_xhi[(size_t)MTOT * KDIM];
__device__ __nv_bfloat16 g_xlo[(size_t)MTOT * KDIM];
__device__ __nv_bfloat16 g_wihi[(size_t)EMB * KDIM];
__device__ __nv_bfloat16 g_wilo[(size_t)EMB * KDIM];
__device__ __nv_bfloat16 g_wohi[(size_t)EMB * KDIM];
__device__ __nv_bfloat16 g_wolo[(size_t)EMB * KDIM];
__device__ float         g_v[(size_t)MTOT * EMB];
__device__ __nv_bfloat16 g_atthi[(size_t)MTOT * EMB];
__device__ __nv_bfloat16 g_attlo[(size_t)MTOT * EMB];
__device__ float         g_cst[BATCH * 2 * 128];

__constant__ int c_pos[8] = {0, 1, 2, 3, 4, 0, 1, 2};
__constant__ float c_wtab[8] = {
    1.0f, 0.60653065971263342f, 0.13533528323661270f, 0.011108996538242306f,
    3.3546262790251185e-4f, 3.7266531720786709e-6f, 1.5229979744712628e-8f,
    2.2897348456455531e-11f
};

// ---------------- PTX helpers ----------------
__device__ __forceinline__ uint32_t smem_u32(const void* p) {
    uint32_t a;
    asm("{ .reg .u64 t; cvta.to.shared.u64 t, %1; cvt.u32.u64 %0, t; }" : "=r"(a) : "l"(p));
    return a;
}
__device__ __forceinline__ void cp16(uint32_t dst, const void* src) {
    asm volatile("cp.async.cg.shared.global [%0], [%1], 16;" :: "r"(dst), "l"(src) : "memory");
}
__device__ __forceinline__ void cp_commit() { asm volatile("cp.async.commit_group;" ::: "memory"); }
__device__ __forceinline__ void cp_wait1()  { asm volatile("cp.async.wait_group 1;" ::: "memory"); }
__device__ __forceinline__ void cp_wait2()  { asm volatile("cp.async.wait_group 2;" ::: "memory"); }

__device__ __forceinline__ void ldx4(uint32_t* r, uint32_t addr) {
    asm volatile("ldmatrix.sync.aligned.m8n8.x4.shared.b16 {%0,%1,%2,%3}, [%4];"
                 : "=r"(r[0]), "=r"(r[1]), "=r"(r[2]), "=r"(r[3]) : "r"(addr));
}
__device__ __forceinline__ void mma16816(float* c, const uint32_t* a, const uint32_t* b) {
    asm volatile("mma.sync.aligned.m16n8k16.row.col.f32.bf16.bf16.f32 "
                 "{%0,%1,%2,%3}, {%4,%5,%6,%7}, {%8,%9}, {%0,%1,%2,%3};"
                 : "+f"(c[0]), "+f"(c[1]), "+f"(c[2]), "+f"(c[3])
                 : "r"(a[0]), "r"(a[1]), "r"(a[2]), "r"(a[3]), "r"(b[0]), "r"(b[1]));
}

// ---------------------------------------------------------------------------
// bf16x3 mma.sync GEMM:  C[M,N](f32) = (Ah+Al)[M,K] · (Bh+Bl)[N,K]^T
// Cross-chunk fragment double-buffering: MMAs of chunk i use registers loaded
// in iteration i-1; iteration i's ldmatrix fetch chunk i+1. No MMA waits on
// an LDSM issued in its own iteration.
// ---------------------------------------------------------------------------
__device__ __forceinline__ void load_chunk(
    uint32_t sb, int stage, int k0, int row0, int col0,
    const __nv_bfloat16* __restrict__ Ah, const __nv_bfloat16* __restrict__ Al,
    const __nv_bfloat16* __restrict__ Bh, const __nv_bfloat16* __restrict__ Bl, int tid)
{
    const uint32_t st  = sb + stage * STAGE_BYTES;
    const uint32_t off = tid * RSTRIDE;
    const size_t ga = (size_t)(row0 + tid) * KDIM + k0;
    const size_t gb = (size_t)(col0 + tid) * KDIM + k0;
    cp16(st + A_HI + off,      Ah + ga);
    cp16(st + A_HI + off + 16, Ah + ga + 8);
    cp16(st + A_LO + off,      Al + ga);
    cp16(st + A_LO + off + 16, Al + ga + 8);
    cp16(st + B_HI + off,      Bh + gb);
    cp16(st + B_HI + off + 16, Bh + gb + 8);
    cp16(st + B_LO + off,      Bl + gb);
    cp16(st + B_LO + off + 16, Bl + gb + 8);
    cp_commit();
}

#define LOAD_A_FRAG(T, AH, AL, STN) { \
    const uint32_t addr_ = (STN) + a_off + (T) * (16 * RSTRIDE); \
    ldx4(AH[T], addr_ + A_HI); \
    ldx4(AL[T], addr_ + A_LO); }

#define LOAD_B_FRAG(P, BH, BL, STN) { \
    const uint32_t addr_ = (STN) + b_off + (P) * (16 * RSTRIDE); \
    uint32_t r_[4]; \
    ldx4(r_, addr_ + B_HI); \
    BH[2*(P)][0]=r_[0]; BH[2*(P)][1]=r_[2]; BH[2*(P)+1][0]=r_[1]; BH[2*(P)+1][1]=r_[3]; \
    ldx4(r_, addr_ + B_LO); \
    BL[2*(P)][0]=r_[0]; BL[2*(P)][1]=r_[2]; BL[2*(P)+1][0]=r_[1]; BL[2*(P)+1][1]=r_[3]; }

// One chunk: MMA on CUR frag set, load NXT frag set (chunk I+1), prefetch I+3.
#define STEP(I, CAH, CAL, CBH, CBL, NAH, NAL, NBH, NBL) { \
    cp_wait1(); __syncthreads(); \
    if ((I) + 3 < NCHUNK) \
        load_chunk(sb, ((I) + 3) & 3, ((I) + 3) * BK, row0, col0, Ah, Al, Bh, Bl, tid); \
    else cp_commit(); \
    const uint32_t stn_ = sb + (((I) + 1) & 3) * STAGE_BYTES; \
    _Pragma("unroll") \
    for (int mt = 0; mt < 4; ++mt) { \
        LOAD_A_FRAG(mt, NAH, NAL, stn_); \
        _Pragma("unroll") \
        for (int nt = 0; nt < 8; ++nt) mma16816(acc[mt][nt], CAH[mt], CBH[nt]); \
    } \
    _Pragma("unroll") \
    for (int mt = 0; mt < 4; ++mt) { \
        LOAD_B_FRAG(mt, NBH, NBL, stn_); \
        _Pragma("unroll") \
        for (int nt = 0; nt < 8; ++nt) mma16816(acc[mt][nt], CAH[mt], CBL[nt]); \
    } \
    _Pragma("unroll") \
    for (int mt = 0; mt < 4; ++mt) \
        _Pragma("unroll") \
        for (int nt = 0; nt < 8; ++nt) mma16816(acc[mt][nt], CAL[mt], CBH[nt]); \
}

__global__ __launch_bounds__(GTHREADS, 2)
void gemm_bf16x3(const __nv_bfloat16* __restrict__ Ah, const __nv_bfloat16* __restrict__ Al,
                 const __nv_bfloat16* __restrict__ Bh, const __nv_bfloat16* __restrict__ Bl,
                 float* __restrict__ C)
{
    extern __shared__ char smem[];
    const uint32_t sb = smem_u32(smem);
    const int tid  = threadIdx.x;
    const int lane = tid & 31, wid = tid >> 5;
    const int wm = (wid & 1) * 64, wn = (wid >> 1) * 64;
    const int row0 = blockIdx.y * BM, col0 = blockIdx.x * BN;

    float acc[4][8][4];
#pragma unroll
    for (int i = 0; i < 4; ++i)
#pragma unroll
        for (int j = 0; j < 8; ++j)
#pragma unroll
            for (int k = 0; k < 4; ++k) acc[i][j][k] = 0.f;

    const uint32_t a_off = (wm + (lane & 15)) * RSTRIDE + ((lane >> 4) << 4);
    const uint32_t b_off = (wn + (lane & 15)) * RSTRIDE + ((lane >> 4) << 4);

    // prologue: chunks 0,1,2 into stages 0,1,2
    load_chunk(sb, 0, 0 * BK, row0, col0, Ah, Al, Bh, Bl, tid);
    load_chunk(sb, 1, 1 * BK, row0, col0, Ah, Al, Bh, Bl, tid);
    load_chunk(sb, 2, 2 * BK, row0, col0, Ah, Al, Bh, Bl, tid);

    uint32_t ah0[4][4], al0[4][4], bh0[8][2], bl0[8][2];
    uint32_t ah1[4][4], al1[4][4], bh1[8][2], bl1[8][2];

    // preload frags of chunk 0 (stage 0)
    cp_wait2();
    __syncthreads();
#pragma unroll
    for (int t = 0; t < 4; ++t) LOAD_A_FRAG(t, ah0, al0, sb);
#pragma unroll
    for (int p = 0; p < 4; ++p) LOAD_B_FRAG(p, bh0, bl0, sb);

    for (int i = 0; i < NCHUNK; i += 2) {
        STEP(i,     ah0, al0, bh0, bl0, ah1, al1, bh1, bl1);
        STEP(i + 1, ah1, al1, bh1, bl1, ah0, al0, bh0, bl0);
    }

    // epilogue: fp32 direct store
#pragma unroll
    for (int mt = 0; mt < 4; ++mt) {
        const int m = row0 + wm + mt * 16 + (lane >> 2);
#pragma unroll
        for (int nt = 0; nt < 8; ++nt) {
            const int n = col0 + wn + nt * 8 + (lane & 3) * 2;
            *(float2*)(C + (size_t)m * EMB + n)       = make_float2(acc[mt][nt][0], acc[mt][nt][1]);
            *(float2*)(C + (size_t)(m + 8) * EMB + n) = make_float2(acc[mt][nt][2], acc[mt][nt][3]);
        }
    }
}

// ---------------------------------------------------------------------------
// fp32 -> bf16 hi/lo split
// ---------------------------------------------------------------------------
__global__ __launch_bounds__(256)
void split_kernel(const float* __restrict__ src, __nv_bfloat16* __restrict__ hi,
                  __nv_bfloat16* __restrict__ lo, int n)
{
    int i = (blockIdx.x * 256 + threadIdx.x) * 4;
    if (i >= n) return;
    float4 v = *(const float4*)(src + i);
    float f[4] = {v.x, v.y, v.z, v.w};
    __nv_bfloat16 h[4], l[4];
#pragma unroll
    for (int j = 0; j < 4; ++j) {
        h[j] = __float2bfloat16(f[j]);
        l[j] = __float2bfloat16(f[j] - __bfloat162float(h[j]));
    }
    *(uint2*)(hi + i) = *(uint2*)h;
    *(uint2*)(lo + i) = *(uint2*)l;
}

// ---------------------------------------------------------------------------
// attention: banded Gaussian conv + constant heads; emits bf16 hi/lo
// ---------------------------------------------------------------------------
__global__ void attn_const_kernel(const float* __restrict__ v, float* __restrict__ cst)
{
    const int b = blockIdx.x, which = blockIdx.y, p = threadIdx.x;
    const int h = which ? 4 : 3;
    float Z = 0.f, acc = 0.f;
#pragma unroll
    for (int j = 0; j < 8; ++j) {
        const int   k = which ? (L_SEQ - 1 - j) : j;
        const float w = c_wtab[j];
        Z += w;
        acc += w * v[((size_t)b * L_SEQ + k) * EMB + h * 128 + p];
    }
    cst[(b * 2 + which) * 128 + p] = acc / Z;
}

#define QT 16
#define CT 256
#define KT 32

__global__ __launch_bounds__(256)
void attn_kernel(const float* __restrict__ v, __nv_bfloat16* __restrict__ ahi,
                 __nv_bfloat16* __restrict__ alo, const float* __restrict__ cst)
{
    const int b = blockIdx.z, q0 = blockIdx.y * QT, c0 = blockIdx.x * CT;
    const int tid = threadIdx.x;
    __shared__ float vt[KT][CT];

    const float* vb = v + (size_t)b * L_SEQ * EMB;
#pragma unroll
    for (int i = 0; i < 8; ++i) {
        const int id = tid + i * 256;
        const int kb = id >> 6, cc = (id & 63) << 2;
        const int k  = q0 - 8 + kb;
        float4 val = make_float4(0.f, 0.f, 0.f, 0.f);
        if (k >= 0 && k < L_SEQ) val = *(const float4*)(vb + (size_t)k * EMB + c0 + cc);
        *(float4*)&vt[kb][cc] = val;
    }
    __syncthreads();

    const int c = c0 + tid, h = c >> 7, pos = c_pos[h];
    const size_t obase = ((size_t)b * L_SEQ + q0) * EMB + c;

    if (pos <= 2) {
        const int off = (pos == 0) ? 0 : (pos == 1 ? -1 : 1);
#pragma unroll
        for (int qq = 0; qq < QT; ++qq) {
            const int cen = q0 + qq + off;
            const int k0 = max(0, cen - 7), k1 = min(L_SEQ - 1, cen + 7);
            float Z = 0.f, acc = 0.f;
            for (int k = k0; k <= k1; ++k) {
                const int   d = k - cen;
                const float w = c_wtab[d < 0 ? -d : d];
                Z += w;
                acc += w * vt[k - q0 + 8][tid];
            }
            const float r = acc / Z;
            __nv_bfloat16 hh = __float2bfloat16(r);
            ahi[obase + (size_t)qq * EMB] = hh;
            alo[obase + (size_t)qq * EMB] = __float2bfloat16(r - __bfloat162float(hh));
        }
    } else {
        const float r = cst[(b * 2 + (pos == 4)) * 128 + (c & 127)];
        __nv_bfloat16 hh = __float2bfloat16(r);
        __nv_bfloat16 ll = __float2bfloat16(r - __bfloat162float(hh));
#pragma unroll
        for (int qq = 0; qq < QT; ++qq) {
            ahi[obase + (size_t)qq * EMB] = hh;
            alo[obase + (size_t)qq * EMB] = ll;
        }
    }
}

// ---------------------------------------------------------------------------
extern "C" void kernel_launch(void* const* d_in, const int* in_sizes, int n_in,
                              void* d_out, int out_size)
{
    const float* x     = (const float*)d_in[0];
    const float* W_in  = (const float*)d_in[1];
    const float* W_out = (const float*)d_in[2];
    float* out = (float*)d_out;

    __nv_bfloat16 *xhi, *xlo, *wihi, *wilo, *wohi, *wolo, *athi, *atlo;
    float *v, *cst;
    cudaGetSymbolAddress((void**)&xhi,  g_xhi);
    cudaGetSymbolAddress((void**)&xlo,  g_xlo);
    cudaGetSymbolAddress((void**)&wihi, g_wihi);
    cudaGetSymbolAddress((void**)&wilo, g_wilo);
    cudaGetSymbolAddress((void**)&wohi, g_wohi);
    cudaGetSymbolAddress((void**)&wolo, g_wolo);
    cudaGetSymbolAddress((void**)&athi, g_atthi);
    cudaGetSymbolAddress((void**)&atlo, g_attlo);
    cudaGetSymbolAddress((void**)&v,    g_v);
    cudaGetSymbolAddress((void**)&cst,  g_cst);

    static bool attr_done = false;
    if (!attr_done) {
        cudaFuncSetAttribute(gemm_bf16x3, cudaFuncAttributeMaxDynamicSharedMemorySize, SMEM_BYTES);
        attr_done = true;
    }

    const int NX = MTOT * KDIM, NW = EMB * KDIM;
    split_kernel<<<NX / (256 * 4), 256>>>(x, xhi, xlo, NX);
    split_kernel<<<NW / (256 * 4), 256>>>(W_in,  wihi, wilo, NW);
    split_kernel<<<NW / (256 * 4), 256>>>(W_out, wohi, wolo, NW);

    const dim3 ggrid(EMB / BN, MTOT / BM);   // (8, 128)
    gemm_bf16x3<<<ggrid, GTHREADS, SMEM_BYTES>>>(xhi, xlo, wihi, wilo, v);

    attn_const_kernel<<<dim3(BATCH, 2), 128>>>(v, cst);
    attn_kernel<<<dim3(EMB / CT, L_SEQ / QT, BATCH), 256>>>(v, athi, atlo, cst);

    gemm_bf16x3<<<ggrid, GTHREADS, SMEM_BYTES>>>(athi, atlo, wohi, wolo, out);
}

// round 9
// speedup vs baseline: 1.5762x; 1.5762x over previous
#include <cuda_runtime.h>
#include <cuda_fp16.h>
#include <cstdint>

#define L_SEQ 2048
#define BATCH 8
#define EMB   1024
#define KDIM  1024
#define MTOT  (BATCH * L_SEQ)   // 16384

// ---- GEMM tiling: CTA 128x128, 4 warps (2x2), warp tile 64x64, BK=16 ----
#define BM 128
#define BN 128
#define BK 16
#define NCHUNK (KDIM / BK)      // 64
#define GTHREADS 128

// smem rows padded to 48B (32B data + 16B pad): 20-word stride is a perfect
// bank permutation mod 32 -> conflict-free ldmatrix without swizzle.
#define RSTRIDE 48
#define A_OFF 0
#define B_OFF (BM * RSTRIDE)                 // 6144
#define STAGE_BYTES (2 * BM * RSTRIDE)       // 12288
#define SMEM_BYTES (2 * STAGE_BYTES)         // 24576

// ---------------- scratch (device globals) ----------------
__device__ __half g_xh[(size_t)MTOT * KDIM];
__device__ __half g_wih[(size_t)EMB * KDIM];
__device__ __half g_woh[(size_t)EMB * KDIM];
__device__ float  g_v[(size_t)MTOT * EMB];
__device__ __half g_att[(size_t)MTOT * EMB];
__device__ float  g_cst[BATCH * 2 * 128];

__constant__ int c_pos[8] = {0, 1, 2, 3, 4, 0, 1, 2};
__constant__ float c_wtab[8] = {
    1.0f, 0.60653065971263342f, 0.13533528323661270f, 0.011108996538242306f,
    3.3546262790251185e-4f, 3.7266531720786709e-6f, 1.5229979744712628e-8f,
    2.2897348456455531e-11f
};

// ---------------- PTX helpers ----------------
__device__ __forceinline__ uint32_t smem_u32(const void* p) {
    uint32_t a;
    asm("{ .reg .u64 t; cvta.to.shared.u64 t, %1; cvt.u32.u64 %0, t; }" : "=r"(a) : "l"(p));
    return a;
}
__device__ __forceinline__ void cp16(uint32_t dst, const void* src) {
    asm volatile("cp.async.cg.shared.global [%0], [%1], 16;" :: "r"(dst), "l"(src) : "memory");
}
__device__ __forceinline__ void cp_commit() { asm volatile("cp.async.commit_group;" ::: "memory"); }
__device__ __forceinline__ void cp_wait0()  { asm volatile("cp.async.wait_group 0;" ::: "memory"); }

__device__ __forceinline__ void ldx4(uint32_t* r, uint32_t addr) {
    asm volatile("ldmatrix.sync.aligned.m8n8.x4.shared.b16 {%0,%1,%2,%3}, [%4];"
                 : "=r"(r[0]), "=r"(r[1]), "=r"(r[2]), "=r"(r[3]) : "r"(addr));
}
__device__ __forceinline__ void mma16816(float* c, const uint32_t* a, const uint32_t* b) {
    asm volatile("mma.sync.aligned.m16n8k16.row.col.f32.f16.f16.f32 "
                 "{%0,%1,%2,%3}, {%4,%5,%6,%7}, {%8,%9}, {%0,%1,%2,%3};"
                 : "+f"(c[0]), "+f"(c[1]), "+f"(c[2]), "+f"(c[3])
                 : "r"(a[0]), "r"(a[1]), "r"(a[2]), "r"(a[3]), "r"(b[0]), "r"(b[1]));
}

// ---------------------------------------------------------------------------
// fp16 mma.sync GEMM:  C[M,N](f32) = A[M,K] · B[N,K]^T
// ---------------------------------------------------------------------------
__device__ __forceinline__ void load_chunk(
    uint32_t sb, int stage, int k0, int row0, int col0,
    const __half* __restrict__ A, const __half* __restrict__ B, int tid)
{
    // 128 threads: each thread owns one row of A and one row of B (2x16B each)
    const uint32_t st  = sb + stage * STAGE_BYTES;
    const uint32_t off = tid * RSTRIDE;
    const size_t ga = (size_t)(row0 + tid) * KDIM + k0;
    const size_t gb = (size_t)(col0 + tid) * KDIM + k0;
    cp16(st + A_OFF + off,      A + ga);
    cp16(st + A_OFF + off + 16, A + ga + 8);
    cp16(st + B_OFF + off,      B + gb);
    cp16(st + B_OFF + off + 16, B + gb + 8);
    cp_commit();
}

__global__ __launch_bounds__(GTHREADS, 2)
void gemm_f16(const __half* __restrict__ A, const __half* __restrict__ B,
              float* __restrict__ C)
{
    __shared__ char smem[SMEM_BYTES];
    const uint32_t sb = smem_u32(smem);
    const int tid  = threadIdx.x;
    const int lane = tid & 31, wid = tid >> 5;
    const int wm = (wid & 1) * 64, wn = (wid >> 1) * 64;
    const int row0 = blockIdx.y * BM, col0 = blockIdx.x * BN;

    float acc[4][8][4];
#pragma unroll
    for (int i = 0; i < 4; ++i)
#pragma unroll
        for (int j = 0; j < 8; ++j)
#pragma unroll
            for (int k = 0; k < 4; ++k) acc[i][j][k] = 0.f;

    // per-lane ldmatrix source offsets (within a matrix block)
    const uint32_t a_off = (wm + (lane & 15)) * RSTRIDE + ((lane >> 4) << 4);
    const uint32_t b_off = (wn + (lane & 15)) * RSTRIDE + ((lane >> 4) << 4);

    load_chunk(sb, 0, 0, row0, col0, A, B, tid);

    for (int i = 0; i < NCHUNK; ++i) {
        cp_wait0();              // chunk i landed (only group in flight)
        __syncthreads();         // chunk i visible AND frags of i-1 consumed

        const uint32_t st = sb + (i & 1) * STAGE_BYTES;

        // ---- fragment loads for chunk i ----
        uint32_t ah[4][4];
#pragma unroll
        for (int t = 0; t < 4; ++t)
            ldx4(ah[t], st + A_OFF + a_off + t * (16 * RSTRIDE));
        uint32_t bh[8][2];
#pragma unroll
        for (int p = 0; p < 4; ++p) {
            uint32_t r[4];
            ldx4(r, st + B_OFF + b_off + p * (16 * RSTRIDE));
            bh[2*p][0] = r[0]; bh[2*p][1] = r[2]; bh[2*p+1][0] = r[1]; bh[2*p+1][1] = r[3];
        }

        // ---- prefetch chunk i+1 (safe: past own frag loads; the sync above
        // ordered everyone's reads of that buffer from iteration i-1) ----
        if (i + 1 < NCHUNK)
            load_chunk(sb, (i + 1) & 1, (i + 1) * BK, row0, col0, A, B, tid);

        // ---- 32 HMMAs ----
#pragma unroll
        for (int mt = 0; mt < 4; ++mt)
#pragma unroll
            for (int nt = 0; nt < 8; ++nt)
                mma16816(acc[mt][nt], ah[mt], bh[nt]);
    }

    // epilogue: fp32 direct store
#pragma unroll
    for (int mt = 0; mt < 4; ++mt) {
        const int m = row0 + wm + mt * 16 + (lane >> 2);
#pragma unroll
        for (int nt = 0; nt < 8; ++nt) {
            const int n = col0 + wn + nt * 8 + (lane & 3) * 2;
            *(float2*)(C + (size_t)m * EMB + n)       = make_float2(acc[mt][nt][0], acc[mt][nt][1]);
            *(float2*)(C + (size_t)(m + 8) * EMB + n) = make_float2(acc[mt][nt][2], acc[mt][nt][3]);
        }
    }
}

// ---------------------------------------------------------------------------
// fp32 -> fp16 convert
// ---------------------------------------------------------------------------
__global__ __launch_bounds__(256)
void cvt_kernel(const float* __restrict__ src, __half* __restrict__ dst, int n)
{
    int i = (blockIdx.x * 256 + threadIdx.x) * 4;
    if (i >= n) return;
    float4 v = *(const float4*)(src + i);
    __half h[4] = { __float2half_rn(v.x), __float2half_rn(v.y),
                    __float2half_rn(v.z), __float2half_rn(v.w) };
    *(uint2*)(dst + i) = *(uint2*)h;
}

// ---------------------------------------------------------------------------
// attention: banded Gaussian conv + constant heads; emits fp16
// ---------------------------------------------------------------------------
__global__ void attn_const_kernel(const float* __restrict__ v, float* __restrict__ cst)
{
    const int b = blockIdx.x, which = blockIdx.y, p = threadIdx.x;
    const int h = which ? 4 : 3;
    float Z = 0.f, acc = 0.f;
#pragma unroll
    for (int j = 0; j < 8; ++j) {
        const int   k = which ? (L_SEQ - 1 - j) : j;
        const float w = c_wtab[j];
        Z += w;
        acc += w * v[((size_t)b * L_SEQ + k) * EMB + h * 128 + p];
    }
    cst[(b * 2 + which) * 128 + p] = acc / Z;
}

#define QT 16
#define CT 256
#define KT 32

__global__ __launch_bounds__(256)
void attn_kernel(const float* __restrict__ v, __half* __restrict__ att,
                 const float* __restrict__ cst)
{
    const int b = blockIdx.z, q0 = blockIdx.y * QT, c0 = blockIdx.x * CT;
    const int tid = threadIdx.x;
    __shared__ float vt[KT][CT];

    const float* vb = v + (size_t)b * L_SEQ * EMB;
#pragma unroll
    for (int i = 0; i < 8; ++i) {
        const int id = tid + i * 256;
        const int kb = id >> 6, cc = (id & 63) << 2;
        const int k  = q0 - 8 + kb;
        float4 val = make_float4(0.f, 0.f, 0.f, 0.f);
        if (k >= 0 && k < L_SEQ) val = *(const float4*)(vb + (size_t)k * EMB + c0 + cc);
        *(float4*)&vt[kb][cc] = val;
    }
    __syncthreads();

    const int c = c0 + tid, h = c >> 7, pos = c_pos[h];
    const size_t obase = ((size_t)b * L_SEQ + q0) * EMB + c;

    if (pos <= 2) {
        const int off = (pos == 0) ? 0 : (pos == 1 ? -1 : 1);
#pragma unroll
        for (int qq = 0; qq < QT; ++qq) {
            const int cen = q0 + qq + off;
            const int k0 = max(0, cen - 7), k1 = min(L_SEQ - 1, cen + 7);
            float Z = 0.f, acc = 0.f;
            for (int k = k0; k <= k1; ++k) {
                const int   d = k - cen;
                const float w = c_wtab[d < 0 ? -d : d];
                Z += w;
                acc += w * vt[k - q0 + 8][tid];
            }
            att[obase + (size_t)qq * EMB] = __float2half_rn(acc / Z);
        }
    } else {
        const __half hh = __float2half_rn(cst[(b * 2 + (pos == 4)) * 128 + (c & 127)]);
#pragma unroll
        for (int qq = 0; qq < QT; ++qq)
            att[obase + (size_t)qq * EMB] = hh;
    }
}

// ---------------------------------------------------------------------------
extern "C" void kernel_launch(void* const* d_in, const int* in_sizes, int n_in,
                              void* d_out, int out_size)
{
    const float* x     = (const float*)d_in[0];
    const float* W_in  = (const float*)d_in[1];
    const float* W_out = (const float*)d_in[2];
    float* out = (float*)d_out;

    __half *xh, *wih, *woh, *att;
    float *v, *cst;
    cudaGetSymbolAddress((void**)&xh,  g_xh);
    cudaGetSymbolAddress((void**)&wih, g_wih);
    cudaGetSymbolAddress((void**)&woh, g_woh);
    cudaGetSymbolAddress((void**)&att, g_att);
    cudaGetSymbolAddress((void**)&v,   g_v);
    cudaGetSymbolAddress((void**)&cst, g_cst);

    const int NX = MTOT * KDIM, NW = EMB * KDIM;
    cvt_kernel<<<NX / (256 * 4), 256>>>(x, xh, NX);
    cvt_kernel<<<NW / (256 * 4), 256>>>(W_in,  wih, NW);
    cvt_kernel<<<NW / (256 * 4), 256>>>(W_out, woh, NW);

    const dim3 ggrid(EMB / BN, MTOT / BM);   // (8, 128)
    gemm_f16<<<ggrid, GTHREADS>>>(xh, wih, v);

    attn_const_kernel<<<dim3(BATCH, 2), 128>>>(v, cst);
    attn_kernel<<<dim3(EMB / CT, L_SEQ / QT, BATCH), 256>>>(v, att, cst);

    gemm_f16<<<ggrid, GTHREADS>>>(att, woh, out);
}

// round 11
// speedup vs baseline: 2.4334x; 1.5438x over previous
#include <cuda_runtime.h>
#include <cuda_fp16.h>
#include <cstdint>

#define L_SEQ 2048
#define BATCH 8
#define EMB   1024
#define KDIM  1024
#define MTOT  (BATCH * L_SEQ)   // 16384

// ---- GEMM tiling: CTA 128x128, 4 warps (2x2), warp tile 64x64, BK=32 ----
#define BM 128
#define BN 128
#define BK 32
#define NCHUNK (KDIM / BK)      // 32
#define GTHREADS 128
#define NSTAGE 3

// rows are 64B data padded to 80B: 20-word stride -> banks (20r mod 32) all
// distinct over 8 consecutive rows => conflict-free ldmatrix, no swizzle.
#define RSTRIDE 80
#define A_OFF 0
#define B_OFF (BM * RSTRIDE)                 // 10240
#define STAGE_BYTES (2 * BM * RSTRIDE)       // 20480
#define SMEM_BYTES (NSTAGE * STAGE_BYTES)    // 61440

// ---------------- scratch (device globals) ----------------
__device__ __half g_xh[(size_t)MTOT * KDIM];
__device__ __half g_wih[(size_t)EMB * KDIM];
__device__ __half g_woh[(size_t)EMB * KDIM];
__device__ __half g_v[(size_t)MTOT * EMB];
__device__ __half g_att[(size_t)MTOT * EMB];
__device__ float  g_cst[BATCH * 2 * 128];

__constant__ int c_pos[8] = {0, 1, 2, 3, 4, 0, 1, 2};
__constant__ float c_wtab[8] = {
    1.0f, 0.60653065971263342f, 0.13533528323661270f, 0.011108996538242306f,
    3.3546262790251185e-4f, 3.7266531720786709e-6f, 1.5229979744712628e-8f,
    2.2897348456455531e-11f
};

// ---------------- PTX helpers ----------------
__device__ __forceinline__ uint32_t smem_u32(const void* p) {
    uint32_t a;
    asm("{ .reg .u64 t; cvta.to.shared.u64 t, %1; cvt.u32.u64 %0, t; }" : "=r"(a) : "l"(p));
    return a;
}
__device__ __forceinline__ void cp16(uint32_t dst, const void* src) {
    asm volatile("cp.async.cg.shared.global [%0], [%1], 16;" :: "r"(dst), "l"(src) : "memory");
}
__device__ __forceinline__ void cp_commit() { asm volatile("cp.async.commit_group;" ::: "memory"); }
__device__ __forceinline__ void cp_wait1()  { asm volatile("cp.async.wait_group 1;" ::: "memory"); }

__device__ __forceinline__ void ldx4(uint32_t* r, uint32_t addr) {
    asm volatile("ldmatrix.sync.aligned.m8n8.x4.shared.b16 {%0,%1,%2,%3}, [%4];"
                 : "=r"(r[0]), "=r"(r[1]), "=r"(r[2]), "=r"(r[3]) : "r"(addr));
}
__device__ __forceinline__ void mma16816(float* c, const uint32_t* a, const uint32_t* b) {
    asm volatile("mma.sync.aligned.m16n8k16.row.col.f32.f16.f16.f32 "
                 "{%0,%1,%2,%3}, {%4,%5,%6,%7}, {%8,%9}, {%0,%1,%2,%3};"
                 : "+f"(c[0]), "+f"(c[1]), "+f"(c[2]), "+f"(c[3])
                 : "r"(a[0]), "r"(a[1]), "r"(a[2]), "r"(a[3]), "r"(b[0]), "r"(b[1]));
}

// ---------------------------------------------------------------------------
// fp16 mma.sync GEMM:  C[M,N] = A[M,K] · B[N,K]^T   (OutT = __half or float)
// ---------------------------------------------------------------------------
__device__ __forceinline__ void load_chunk(
    uint32_t sb, int stage, int k0, int row0, int col0,
    const __half* __restrict__ A, const __half* __restrict__ B, int tid)
{
    // 128 threads: one 64B A row + one 64B B row each (4x16B per row)
    const uint32_t st  = sb + stage * STAGE_BYTES;
    const uint32_t off = tid * RSTRIDE;
    const size_t ga = (size_t)(row0 + tid) * KDIM + k0;
    const size_t gb = (size_t)(col0 + tid) * KDIM + k0;
#pragma unroll
    for (int c = 0; c < 4; ++c) {
        cp16(st + A_OFF + off + c * 16, A + ga + c * 8);
        cp16(st + B_OFF + off + c * 16, B + gb + c * 8);
    }
    cp_commit();
}

template <typename OutT>
__global__ __launch_bounds__(GTHREADS, 2)
void gemm_f16(const __half* __restrict__ A, const __half* __restrict__ B,
              OutT* __restrict__ C)
{
    extern __shared__ char smem[];
    const uint32_t sb = smem_u32(smem);
    const int tid  = threadIdx.x;
    const int lane = tid & 31, wid = tid >> 5;
    const int wm = (wid & 1) * 64, wn = (wid >> 1) * 64;
    const int row0 = blockIdx.y * BM, col0 = blockIdx.x * BN;

    float acc[4][8][4];
#pragma unroll
    for (int i = 0; i < 4; ++i)
#pragma unroll
        for (int j = 0; j < 8; ++j)
#pragma unroll
            for (int k = 0; k < 4; ++k) acc[i][j][k] = 0.f;

    const uint32_t a_off = (wm + (lane & 15)) * RSTRIDE + ((lane >> 4) << 4);
    const uint32_t b_off = (wn + (lane & 15)) * RSTRIDE + ((lane >> 4) << 4);

    load_chunk(sb, 0, 0,  row0, col0, A, B, tid);
    load_chunk(sb, 1, BK, row0, col0, A, B, tid);

    int stage = 0;
    for (int i = 0; i < NCHUNK; ++i) {
        cp_wait1();              // chunk i landed (chunk i+1 may be in flight)
        __syncthreads();         // chunk i visible AND frags of i-1 consumed

        // prefetch chunk i+2 into the stage freed at iteration i-1
        if (i + 2 < NCHUNK) {
            int ps = stage + 2; if (ps >= NSTAGE) ps -= NSTAGE;
            load_chunk(sb, ps, (i + 2) * BK, row0, col0, A, B, tid);
        } else {
            cp_commit();         // keep group count for wait1
        }

        const uint32_t st = sb + stage * STAGE_BYTES;

        // two k-slices of 16 within the 32-wide chunk
#pragma unroll
        for (int ks = 0; ks < 2; ++ks) {
            uint32_t ah[4][4];
#pragma unroll
            for (int t = 0; t < 4; ++t)
                ldx4(ah[t], st + A_OFF + a_off + t * (16 * RSTRIDE) + ks * 32);
            uint32_t bh[8][2];
#pragma unroll
            for (int p = 0; p < 4; ++p) {
                uint32_t r[4];
                ldx4(r, st + B_OFF + b_off + p * (16 * RSTRIDE) + ks * 32);
                bh[2*p][0] = r[0]; bh[2*p][1] = r[2];
                bh[2*p+1][0] = r[1]; bh[2*p+1][1] = r[3];
            }
#pragma unroll
            for (int mt = 0; mt < 4; ++mt)
#pragma unroll
                for (int nt = 0; nt < 8; ++nt)
                    mma16816(acc[mt][nt], ah[mt], bh[nt]);
        }

        ++stage; if (stage >= NSTAGE) stage = 0;
    }

    // epilogue
#pragma unroll
    for (int mt = 0; mt < 4; ++mt) {
        const int m = row0 + wm + mt * 16 + (lane >> 2);
#pragma unroll
        for (int nt = 0; nt < 8; ++nt) {
            const int n = col0 + wn + nt * 8 + (lane & 3) * 2;
            if (sizeof(OutT) == 2) {
                __half2* c0 = (__half2*)((__half*)C + (size_t)m * EMB + n);
                __half2* c1 = (__half2*)((__half*)C + (size_t)(m + 8) * EMB + n);
                *c0 = __floats2half2_rn(acc[mt][nt][0], acc[mt][nt][1]);
                *c1 = __floats2half2_rn(acc[mt][nt][2], acc[mt][nt][3]);
            } else {
                *(float2*)((float*)C + (size_t)m * EMB + n) =
                    make_float2(acc[mt][nt][0], acc[mt][nt][1]);
                *(float2*)((float*)C + (size_t)(m + 8) * EMB + n) =
                    make_float2(acc[mt][nt][2], acc[mt][nt][3]);
            }
        }
    }
}

// ---------------------------------------------------------------------------
// fp32 -> fp16 convert
// ---------------------------------------------------------------------------
__global__ __launch_bounds__(256)
void cvt_kernel(const float* __restrict__ src, __half* __restrict__ dst, int n)
{
    int i = (blockIdx.x * 256 + threadIdx.x) * 4;
    if (i >= n) return;
    float4 v = *(const float4*)(src + i);
    __half h[4] = { __float2half_rn(v.x), __float2half_rn(v.y),
                    __float2half_rn(v.z), __float2half_rn(v.w) };
    *(uint2*)(dst + i) = *(uint2*)h;
}

// ---------------------------------------------------------------------------
// attention: banded Gaussian conv + constant heads (fp16 v -> fp16 att)
// ---------------------------------------------------------------------------
__global__ void attn_const_kernel(const __half* __restrict__ v, float* __restrict__ cst)
{
    const int b = blockIdx.x, which = blockIdx.y, p = threadIdx.x;
    const int h = which ? 4 : 3;
    float Z = 0.f, acc = 0.f;
#pragma unroll
    for (int j = 0; j < 8; ++j) {
        const int   k = which ? (L_SEQ - 1 - j) : j;
        const float w = c_wtab[j];
        Z += w;
        acc += w * __half2float(v[((size_t)b * L_SEQ + k) * EMB + h * 128 + p]);
    }
    cst[(b * 2 + which) * 128 + p] = acc / Z;
}

#define QT 16
#define CT 256
#define KT 32

__global__ __launch_bounds__(256)
void attn_kernel(const __half* __restrict__ v, __half* __restrict__ att,
                 const float* __restrict__ cst)
{
    const int b = blockIdx.z, q0 = blockIdx.y * QT, c0 = blockIdx.x * CT;
    const int tid = threadIdx.x;
    __shared__ float vt[KT][CT];

    const __half* vb = v + (size_t)b * L_SEQ * EMB;
#pragma unroll
    for (int i = 0; i < 8; ++i) {
        const int id = tid + i * 256;
        const int kb = id >> 6, cc = (id & 63) << 2;
        const int k  = q0 - 8 + kb;
        float4 val = make_float4(0.f, 0.f, 0.f, 0.f);
        if (k >= 0 && k < L_SEQ) {
            uint2 raw = *(const uint2*)(vb + (size_t)k * EMB + c0 + cc);
            const __half* hp = (const __half*)&raw;
            val = make_float4(__half2float(hp[0]), __half2float(hp[1]),
                              __half2float(hp[2]), __half2float(hp[3]));
        }
        *(float4*)&vt[kb][cc] = val;
    }
    __syncthreads();

    const int c = c0 + tid, h = c >> 7, pos = c_pos[h];
    const size_t obase = ((size_t)b * L_SEQ + q0) * EMB + c;

    if (pos <= 2) {
        const int off = (pos == 0) ? 0 : (pos == 1 ? -1 : 1);
#pragma unroll
        for (int qq = 0; qq < QT; ++qq) {
            const int cen = q0 + qq + off;
            const int k0 = max(0, cen - 7), k1 = min(L_SEQ - 1, cen + 7);
            float Z = 0.f, acc = 0.f;
            for (int k = k0; k <= k1; ++k) {
                const int   d = k - cen;
                const float w = c_wtab[d < 0 ? -d : d];
                Z += w;
                acc += w * vt[k - q0 + 8][tid];
            }
            att[obase + (size_t)qq * EMB] = __float2half_rn(acc / Z);
        }
    } else {
        const __half hh = __float2half_rn(cst[(b * 2 + (pos == 4)) * 128 + (c & 127)]);
#pragma unroll
        for (int qq = 0; qq < QT; ++qq)
            att[obase + (size_t)qq * EMB] = hh;
    }
}

// ---------------------------------------------------------------------------
extern "C" void kernel_launch(void* const* d_in, const int* in_sizes, int n_in,
                              void* d_out, int out_size)
{
    const float* x     = (const float*)d_in[0];
    const float* W_in  = (const float*)d_in[1];
    const float* W_out = (const float*)d_in[2];
    float* out = (float*)d_out;

    __half *xh, *wih, *woh, *att, *v;
    float *cst;
    cudaGetSymbolAddress((void**)&xh,  g_xh);
    cudaGetSymbolAddress((void**)&wih, g_wih);
    cudaGetSymbolAddress((void**)&woh, g_woh);
    cudaGetSymbolAddress((void**)&att, g_att);
    cudaGetSymbolAddress((void**)&v,   g_v);
    cudaGetSymbolAddress((void**)&cst, g_cst);

    static bool attr_done = false;
    if (!attr_done) {
        cudaFuncSetAttribute(gemm_f16<__half>, cudaFuncAttributeMaxDynamicSharedMemorySize, SMEM_BYTES);
        cudaFuncSetAttribute(gemm_f16<float>,  cudaFuncAttributeMaxDynamicSharedMemorySize, SMEM_BYTES);
        attr_done = true;
    }

    const int NX = MTOT * KDIM, NW = EMB * KDIM;
    cvt_kernel<<<NX / (256 * 4), 256>>>(x, xh, NX);
    cvt_kernel<<<NW / (256 * 4), 256>>>(W_in,  wih, NW);
    cvt_kernel<<<NW / (256 * 4), 256>>>(W_out, woh, NW);

    const dim3 ggrid(EMB / BN, MTOT / BM);   // (8, 128)
    gemm_f16<__half><<<ggrid, GTHREADS, SMEM_BYTES>>>(xh, wih, v);

    attn_const_kernel<<<dim3(BATCH, 2), 128>>>(v, cst);
    attn_kernel<<<dim3(EMB / CT, L_SEQ / QT, BATCH), 256>>>(v, att, cst);

    gemm_f16<float><<<ggrid, GTHREADS, SMEM_BYTES>>>(att, woh, out);
}

// round 12
// speedup vs baseline: 4.1946x; 1.7238x over previous
#include <cuda_runtime.h>
#include <cuda_fp16.h>
#include <cstdint>

#define L_SEQ 2048
#define BATCH 8
#define EMB   1024
#define KDIM  1024
#define MTOT  (BATCH * L_SEQ)   // 16384

// ---- GEMM tiling: CTA 128x128, 4 warps (2x2), warp tile 64x64, BK=64 ----
#define BM 128
#define BN 128
#define BK 64
#define NCHUNK (KDIM / BK)      // 16
#define GTHREADS 128
#define NSTAGE 3

// gmem tiled layout: [row_blk][k_blk] tiles of 128 rows x 64 halves = 16 KB,
// rows are 128B, swizzled with the SW128 XOR (bits[6:4] ^= bits[9:7]).
#define TILE_ELEMS (BM * BK)                 // 8192 halves
#define TILE_BYTES (TILE_ELEMS * 2)          // 16384
#define KTILES (KDIM / BK)                   // 16

#define STAGE_BYTES (2 * TILE_BYTES)         // 32768 (A tile + B tile)
#define SM_STAGE0 1024                       // mbarriers live below
#define SMEM_BYTES (SM_STAGE0 + NSTAGE * STAGE_BYTES)   // 99328

__device__ __forceinline__ uint32_t swz(uint32_t off) { return off ^ ((off >> 3) & 0x70); }

// ---------------- scratch (device globals) ----------------
__device__ __half g_xh[(size_t)MTOT * KDIM];   // tiled
__device__ __half g_wih[(size_t)EMB * KDIM];   // tiled
__device__ __half g_woh[(size_t)EMB * KDIM];   // tiled
__device__ __half g_v[(size_t)MTOT * EMB];     // plain (attention input)
__device__ __half g_att[(size_t)MTOT * EMB];   // tiled (GEMM2 A input)
__device__ float  g_cst[BATCH * 2 * 128];

__constant__ int c_pos[8] = {0, 1, 2, 3, 4, 0, 1, 2};
__constant__ float c_wtab[8] = {
    1.0f, 0.60653065971263342f, 0.13533528323661270f, 0.011108996538242306f,
    3.3546262790251185e-4f, 3.7266531720786709e-6f, 1.5229979744712628e-8f,
    2.2897348456455531e-11f
};

// ---------------- PTX helpers ----------------
__device__ __forceinline__ uint32_t smem_u32(const void* p) {
    uint32_t a;
    asm("{ .reg .u64 t; cvta.to.shared.u64 t, %1; cvt.u32.u64 %0, t; }" : "=r"(a) : "l"(p));
    return a;
}
__device__ __forceinline__ void mbar_init(uint32_t a, uint32_t cnt) {
    asm volatile("mbarrier.init.shared.b64 [%0], %1;" :: "r"(a), "r"(cnt) : "memory");
}
__device__ __forceinline__ void mbar_expect_tx(uint32_t a, uint32_t bytes) {
    asm volatile("mbarrier.arrive.expect_tx.shared.b64 _, [%0], %1;" :: "r"(a), "r"(bytes) : "memory");
}
__device__ __forceinline__ void mbar_wait(uint32_t a, uint32_t par) {
    asm volatile("{\n\t.reg .pred P;\n\tWL_%=:\n\t"
        "mbarrier.try_wait.parity.acquire.cta.shared::cta.b64 P, [%0], %1, 0x989680;\n\t"
        "@P bra.uni WD_%=;\n\tbra.uni WL_%=;\n\tWD_%=:\n\t}" :: "r"(a), "r"(par) : "memory");
}
__device__ __forceinline__ void bulk_g2s(uint32_t dst, const void* src, uint32_t bytes, uint32_t mbar) {
    asm volatile("cp.async.bulk.shared::cluster.global.mbarrier::complete_tx::bytes [%0], [%1], %2, [%3];"
                 :: "r"(dst), "l"(src), "r"(bytes), "r"(mbar) : "memory");
}
__device__ __forceinline__ void ldx4(uint32_t* r, uint32_t addr) {
    asm volatile("ldmatrix.sync.aligned.m8n8.x4.shared.b16 {%0,%1,%2,%3}, [%4];"
                 : "=r"(r[0]), "=r"(r[1]), "=r"(r[2]), "=r"(r[3]) : "r"(addr));
}
__device__ __forceinline__ void mma16816(float* c, const uint32_t* a, const uint32_t* b) {
    asm volatile("mma.sync.aligned.m16n8k16.row.col.f32.f16.f16.f32 "
                 "{%0,%1,%2,%3}, {%4,%5,%6,%7}, {%8,%9}, {%0,%1,%2,%3};"
                 : "+f"(c[0]), "+f"(c[1]), "+f"(c[2]), "+f"(c[3])
                 : "r"(a[0]), "r"(a[1]), "r"(a[2]), "r"(a[3]), "r"(b[0]), "r"(b[1]));
}

// ---------------------------------------------------------------------------
// fp16 mma.sync GEMM on TMA bulk copies:  C[M,N] = A[M,K] · B[N,K]^T
// A, B are in the tiled+swizzled layout; C is plain row-major.
// ---------------------------------------------------------------------------
template <typename OutT>
__global__ __launch_bounds__(GTHREADS, 2)
void gemm_f16(const __half* __restrict__ A, const __half* __restrict__ B,
              OutT* __restrict__ C)
{
    extern __shared__ char smem[];
    const uint32_t sb = smem_u32(smem);
    const int tid  = threadIdx.x;
    const int lane = tid & 31, wid = tid >> 5;
    const int wm = (wid & 1) * 64, wn = (wid >> 1) * 64;
    const int row0 = blockIdx.y * BM, col0 = blockIdx.x * BN;

    const __half* Atiles = A + (size_t)blockIdx.y * KTILES * TILE_ELEMS;
    const __half* Btiles = B + (size_t)blockIdx.x * KTILES * TILE_ELEMS;

    float acc[4][8][4];
#pragma unroll
    for (int i = 0; i < 4; ++i)
#pragma unroll
        for (int j = 0; j < 8; ++j)
#pragma unroll
            for (int k = 0; k < 4; ++k) acc[i][j][k] = 0.f;

    if (tid == 0) {
#pragma unroll
        for (int s = 0; s < NSTAGE; ++s) mbar_init(sb + s * 8, 1);
    }
    __syncthreads();

    if (tid == 0) {
#pragma unroll
        for (int c = 0; c < 2; ++c) {
            const uint32_t st = sb + SM_STAGE0 + c * STAGE_BYTES;
            mbar_expect_tx(sb + c * 8, STAGE_BYTES);
            bulk_g2s(st,              Atiles + (size_t)c * TILE_ELEMS, TILE_BYTES, sb + c * 8);
            bulk_g2s(st + TILE_BYTES, Btiles + (size_t)c * TILE_ELEMS, TILE_BYTES, sb + c * 8);
        }
    }

    int stage = 0, phase = 0;
    for (int i = 0; i < NCHUNK; ++i) {
        mbar_wait(sb + stage * 8, phase);   // chunk i resident in stage
        __syncthreads();                    // everyone past iter i-1's frag loads

        if (tid == 0 && i + 2 < NCHUNK) {
            int ps = stage + 2; if (ps >= NSTAGE) ps -= NSTAGE;
            const uint32_t st = sb + SM_STAGE0 + ps * STAGE_BYTES;
            mbar_expect_tx(sb + ps * 8, STAGE_BYTES);
            bulk_g2s(st,              Atiles + (size_t)(i + 2) * TILE_ELEMS, TILE_BYTES, sb + ps * 8);
            bulk_g2s(st + TILE_BYTES, Btiles + (size_t)(i + 2) * TILE_ELEMS, TILE_BYTES, sb + ps * 8);
        }

        const uint32_t stA = sb + SM_STAGE0 + stage * STAGE_BYTES;
        const uint32_t stB = stA + TILE_BYTES;
        const uint32_t csel = ((lane >> 4) << 4);

        // four k-slices of 16 within the 64-wide chunk (rows are 128B)
#pragma unroll
        for (int ks = 0; ks < 4; ++ks) {
            uint32_t ah[4][4];
#pragma unroll
            for (int t = 0; t < 4; ++t) {
                const uint32_t off = (uint32_t)(wm + (lane & 15) + t * 16) * 128 + ks * 32 + csel;
                ldx4(ah[t], stA + swz(off));
            }
            uint32_t bh[8][2];
#pragma unroll
            for (int p = 0; p < 4; ++p) {
                const uint32_t off = (uint32_t)(wn + (lane & 15) + p * 16) * 128 + ks * 32 + csel;
                uint32_t r[4];
                ldx4(r, stB + swz(off));
                bh[2*p][0] = r[0]; bh[2*p][1] = r[2];
                bh[2*p+1][0] = r[1]; bh[2*p+1][1] = r[3];
            }
#pragma unroll
            for (int mt = 0; mt < 4; ++mt)
#pragma unroll
                for (int nt = 0; nt < 8; ++nt)
                    mma16816(acc[mt][nt], ah[mt], bh[nt]);
        }

        ++stage; if (stage >= NSTAGE) { stage = 0; phase ^= 1; }
    }

    // epilogue (plain row-major C)
#pragma unroll
    for (int mt = 0; mt < 4; ++mt) {
        const int m = row0 + wm + mt * 16 + (lane >> 2);
#pragma unroll
        for (int nt = 0; nt < 8; ++nt) {
            const int n = col0 + wn + nt * 8 + (lane & 3) * 2;
            if (sizeof(OutT) == 2) {
                *(__half2*)((__half*)C + (size_t)m * EMB + n) =
                    __floats2half2_rn(acc[mt][nt][0], acc[mt][nt][1]);
                *(__half2*)((__half*)C + (size_t)(m + 8) * EMB + n) =
                    __floats2half2_rn(acc[mt][nt][2], acc[mt][nt][3]);
            } else {
                *(float2*)((float*)C + (size_t)m * EMB + n) =
                    make_float2(acc[mt][nt][0], acc[mt][nt][1]);
                *(float2*)((float*)C + (size_t)(m + 8) * EMB + n) =
                    make_float2(acc[mt][nt][2], acc[mt][nt][3]);
            }
        }
    }
}

// ---------------------------------------------------------------------------
// fp32 plain -> fp16 tiled+swizzled convert ([nrows x KDIM], nrows mult of 128)
// ---------------------------------------------------------------------------
__global__ __launch_bounds__(256)
void cvt_tiled_kernel(const float* __restrict__ src, __half* __restrict__ dst, int n)
{
    int i = (blockIdx.x * 256 + threadIdx.x) * 4;
    if (i >= n) return;
    const int m = i >> 10;            // KDIM = 1024
    const int k = i & 1023;
    float4 v = *(const float4*)(src + i);
    __half h[4] = { __float2half_rn(v.x), __float2half_rn(v.y),
                    __float2half_rn(v.z), __float2half_rn(v.w) };
    const uint32_t tile = (uint32_t)(m >> 7) * KTILES + (k >> 6);
    const uint32_t off  = swz(((uint32_t)(m & 127) << 7) | ((uint32_t)(k & 63) << 1));
    *(uint2*)((char*)dst + (size_t)tile * TILE_BYTES + off) = *(uint2*)h;
}

// ---------------------------------------------------------------------------
// attention: banded Gaussian conv + constant heads (plain fp16 v -> tiled att)
// ---------------------------------------------------------------------------
__global__ void attn_const_kernel(const __half* __restrict__ v, float* __restrict__ cst)
{
    const int b = blockIdx.x, which = blockIdx.y, p = threadIdx.x;
    const int h = which ? 4 : 3;
    float Z = 0.f, acc = 0.f;
#pragma unroll
    for (int j = 0; j < 8; ++j) {
        const int   k = which ? (L_SEQ - 1 - j) : j;
        const float w = c_wtab[j];
        Z += w;
        acc += w * __half2float(v[((size_t)b * L_SEQ + k) * EMB + h * 128 + p]);
    }
    cst[(b * 2 + which) * 128 + p] = acc / Z;
}

#define QT 16
#define CT 256
#define KT 32

__global__ __launch_bounds__(256)
void attn_kernel(const __half* __restrict__ v, __half* __restrict__ att,
                 const float* __restrict__ cst)
{
    const int b = blockIdx.z, q0 = blockIdx.y * QT, c0 = blockIdx.x * CT;
    const int tid = threadIdx.x;
    __shared__ float vt[KT][CT];

    const __half* vb = v + (size_t)b * L_SEQ * EMB;
#pragma unroll
    for (int i = 0; i < 8; ++i) {
        const int id = tid + i * 256;
        const int kb = id >> 6, cc = (id & 63) << 2;
        const int k  = q0 - 8 + kb;
        float4 val = make_float4(0.f, 0.f, 0.f, 0.f);
        if (k >= 0 && k < L_SEQ) {
            uint2 raw = *(const uint2*)(vb + (size_t)k * EMB + c0 + cc);
            const __half* hp = (const __half*)&raw;
            val = make_float4(__half2float(hp[0]), __half2float(hp[1]),
                              __half2float(hp[2]), __half2float(hp[3]));
        }
        *(float4*)&vt[kb][cc] = val;
    }
    __syncthreads();

    const int c = c0 + tid, h = c >> 7, pos = c_pos[h];

    // tiled+swizzled output addressing: element (m, c)
    const int mbase = b * L_SEQ + q0;                       // all qq in same 128-block
    const uint32_t tile = (uint32_t)(mbase >> 7) * KTILES + (c >> 6);
    char* tbase = (char*)att + (size_t)tile * TILE_BYTES;
    const uint32_t cbits = (uint32_t)(c & 63) << 1;

    if (pos <= 2) {
        const int off = (pos == 0) ? 0 : (pos == 1 ? -1 : 1);
#pragma unroll
        for (int qq = 0; qq < QT; ++qq) {
            const int cen = q0 + qq + off;
            const int k0 = max(0, cen - 7), k1 = min(L_SEQ - 1, cen + 7);
            float Z = 0.f, acc = 0.f;
            for (int k = k0; k <= k1; ++k) {
                const int   d = k - cen;
                const float w = c_wtab[d < 0 ? -d : d];
                Z += w;
                acc += w * vt[k - q0 + 8][tid];
            }
            const uint32_t o = swz((((uint32_t)((mbase + qq) & 127)) << 7) | cbits);
            *(__half*)(tbase + o) = __float2half_rn(acc / Z);
        }
    } else {
        const __half hh = __float2half_rn(cst[(b * 2 + (pos == 4)) * 128 + (c & 127)]);
#pragma unroll
        for (int qq = 0; qq < QT; ++qq) {
            const uint32_t o = swz((((uint32_t)((mbase + qq) & 127)) << 7) | cbits);
            *(__half*)(tbase + o) = hh;
        }
    }
}

// ---------------------------------------------------------------------------
extern "C" void kernel_launch(void* const* d_in, const int* in_sizes, int n_in,
                              void* d_out, int out_size)
{
    const float* x     = (const float*)d_in[0];
    const float* W_in  = (const float*)d_in[1];
    const float* W_out = (const float*)d_in[2];
    float* out = (float*)d_out;

    __half *xh, *wih, *woh, *att, *v;
    float *cst;
    cudaGetSymbolAddress((void**)&xh,  g_xh);
    cudaGetSymbolAddress((void**)&wih, g_wih);
    cudaGetSymbolAddress((void**)&woh, g_woh);
    cudaGetSymbolAddress((void**)&att, g_att);
    cudaGetSymbolAddress((void**)&v,   g_v);
    cudaGetSymbolAddress((void**)&cst, g_cst);

    static bool attr_done = false;
    if (!attr_done) {
        cudaFuncSetAttribute(gemm_f16<__half>, cudaFuncAttributeMaxDynamicSharedMemorySize, SMEM_BYTES);
        cudaFuncSetAttribute(gemm_f16<float>,  cudaFuncAttributeMaxDynamicSharedMemorySize, SMEM_BYTES);
        attr_done = true;
    }

    const int NX = MTOT * KDIM, NW = EMB * KDIM;
    cvt_tiled_kernel<<<NX / (256 * 4), 256>>>(x, xh, NX);
    cvt_tiled_kernel<<<NW / (256 * 4), 256>>>(W_in,  wih, NW);
    cvt_tiled_kernel<<<NW / (256 * 4), 256>>>(W_out, woh, NW);

    const dim3 ggrid(EMB / BN, MTOT / BM);   // (8, 128)
    gemm_f16<__half><<<ggrid, GTHREADS, SMEM_BYTES>>>(xh, wih, v);

    attn_const_kernel<<<dim3(BATCH, 2), 128>>>(v, cst);
    attn_kernel<<<dim3(EMB / CT, L_SEQ / QT, BATCH), 256>>>(v, att, cst);

    gemm_f16<float><<<ggrid, GTHREADS, SMEM_BYTES>>>(att, woh, out);
}

// round 14
// speedup vs baseline: 4.6688x; 1.1130x over previous
#include <cuda_runtime.h>
#include <cuda_fp16.h>
#include <cstdint>

#define L_SEQ 2048
#define BATCH 8
#define EMB   1024
#define KDIM  1024
#define MTOT  (BATCH * L_SEQ)   // 16384

// ---- GEMM tiling: CTA 128x128, 4 warps (2x2), warp tile 64x64, BK=64 ----
#define BM 128
#define BN 128
#define BK 64
#define NCHUNK (KDIM / BK)      // 16
#define GTHREADS 128
#define NSTAGE 3

// gmem tiled layout: [row_blk][k_blk] tiles of 128 rows x 64 halves = 16 KB,
// rows are 128B, swizzled with the SW128 XOR (bits[6:4] ^= bits[9:7]).
#define TILE_ELEMS (BM * BK)                 // 8192 halves
#define TILE_BYTES (TILE_ELEMS * 2)          // 16384
#define KTILES (KDIM / BK)                   // 16

#define STAGE_BYTES (2 * TILE_BYTES)         // 32768 (A tile + B tile)
#define SM_STAGE0 1024                       // mbarriers live below
#define SMEM_BYTES (SM_STAGE0 + NSTAGE * STAGE_BYTES)   // 99328

__device__ __forceinline__ uint32_t swz(uint32_t off) { return off ^ ((off >> 3) & 0x70); }

// ---------------- scratch (device globals) ----------------
__device__ __half g_xh[(size_t)MTOT * KDIM];   // tiled
__device__ __half g_wih[(size_t)EMB * KDIM];   // tiled
__device__ __half g_woh[(size_t)EMB * KDIM];   // tiled
__device__ __half g_v[(size_t)MTOT * EMB];     // plain (attention input)
__device__ __half g_att[(size_t)MTOT * EMB];   // tiled (GEMM2 A input)
__device__ float  g_cst[BATCH * 2 * 128];

__constant__ int c_pos[8] = {0, 1, 2, 3, 4, 0, 1, 2};
__constant__ float c_wtab[8] = {
    1.0f, 0.60653065971263342f, 0.13533528323661270f, 0.011108996538242306f,
    3.3546262790251185e-4f, 3.7266531720786709e-6f, 1.5229979744712628e-8f,
    2.2897348456455531e-11f
};

// ---------------- PTX helpers ----------------
__device__ __forceinline__ uint32_t smem_u32(const void* p) {
    uint32_t a;
    asm("{ .reg .u64 t; cvta.to.shared.u64 t, %1; cvt.u32.u64 %0, t; }" : "=r"(a) : "l"(p));
    return a;
}
__device__ __forceinline__ void mbar_init(uint32_t a, uint32_t cnt) {
    asm volatile("mbarrier.init.shared.b64 [%0], %1;" :: "r"(a), "r"(cnt) : "memory");
}
__device__ __forceinline__ void mbar_expect_tx(uint32_t a, uint32_t bytes) {
    asm volatile("mbarrier.arrive.expect_tx.shared.b64 _, [%0], %1;" :: "r"(a), "r"(bytes) : "memory");
}
__device__ __forceinline__ void mbar_wait(uint32_t a, uint32_t par) {
    asm volatile("{\n\t.reg .pred P;\n\tWL_%=:\n\t"
        "mbarrier.try_wait.parity.acquire.cta.shared::cta.b64 P, [%0], %1, 0x989680;\n\t"
        "@P bra.uni WD_%=;\n\tbra.uni WL_%=;\n\tWD_%=:\n\t}" :: "r"(a), "r"(par) : "memory");
}
__device__ __forceinline__ void bulk_g2s(uint32_t dst, const void* src, uint32_t bytes, uint32_t mbar) {
    asm volatile("cp.async.bulk.shared::cluster.global.mbarrier::complete_tx::bytes [%0], [%1], %2, [%3];"
                 :: "r"(dst), "l"(src), "r"(bytes), "r"(mbar) : "memory");
}
__device__ __forceinline__ void ldx4(uint32_t* r, uint32_t addr) {
    asm volatile("ldmatrix.sync.aligned.m8n8.x4.shared.b16 {%0,%1,%2,%3}, [%4];"
                 : "=r"(r[0]), "=r"(r[1]), "=r"(r[2]), "=r"(r[3]) : "r"(addr));
}
__device__ __forceinline__ void mma16816(float* c, const uint32_t* a, const uint32_t* b) {
    asm volatile("mma.sync.aligned.m16n8k16.row.col.f32.f16.f16.f32 "
                 "{%0,%1,%2,%3}, {%4,%5,%6,%7}, {%8,%9}, {%0,%1,%2,%3};"
                 : "+f"(c[0]), "+f"(c[1]), "+f"(c[2]), "+f"(c[3])
                 : "r"(a[0]), "r"(a[1]), "r"(a[2]), "r"(a[3]), "r"(b[0]), "r"(b[1]));
}

// ---------------------------------------------------------------------------
// fp16 mma.sync GEMM on TMA bulk copies:  C[M,N] = A[M,K] · B[N,K]^T
// A, B are in the tiled+swizzled layout; C is plain row-major.
// ---------------------------------------------------------------------------
template <typename OutT>
__global__ __launch_bounds__(GTHREADS, 2)
void gemm_f16(const __half* __restrict__ A, const __half* __restrict__ B,
              OutT* __restrict__ C)
{
    extern __shared__ char smem[];
    const uint32_t sb = smem_u32(smem);
    const int tid  = threadIdx.x;
    const int lane = tid & 31, wid = tid >> 5;
    const int wm = (wid & 1) * 64, wn = (wid >> 1) * 64;
    const int row0 = blockIdx.y * BM, col0 = blockIdx.x * BN;

    const __half* Atiles = A + (size_t)blockIdx.y * KTILES * TILE_ELEMS;
    const __half* Btiles = B + (size_t)blockIdx.x * KTILES * TILE_ELEMS;

    float acc[4][8][4];
#pragma unroll
    for (int i = 0; i < 4; ++i)
#pragma unroll
        for (int j = 0; j < 8; ++j)
#pragma unroll
            for (int k = 0; k < 4; ++k) acc[i][j][k] = 0.f;

    if (tid == 0) {
#pragma unroll
        for (int s = 0; s < NSTAGE; ++s) mbar_init(sb + s * 8, 1);
    }
    __syncthreads();

    if (tid == 0) {
#pragma unroll
        for (int c = 0; c < 2; ++c) {
            const uint32_t st = sb + SM_STAGE0 + c * STAGE_BYTES;
            mbar_expect_tx(sb + c * 8, STAGE_BYTES);
            bulk_g2s(st,              Atiles + (size_t)c * TILE_ELEMS, TILE_BYTES, sb + c * 8);
            bulk_g2s(st + TILE_BYTES, Btiles + (size_t)c * TILE_ELEMS, TILE_BYTES, sb + c * 8);
        }
    }

    int stage = 0, phase = 0;
    for (int i = 0; i < NCHUNK; ++i) {
        mbar_wait(sb + stage * 8, phase);   // chunk i resident in stage
        __syncthreads();                    // everyone past iter i-1's frag loads

        if (tid == 0 && i + 2 < NCHUNK) {
            int ps = stage + 2; if (ps >= NSTAGE) ps -= NSTAGE;
            const uint32_t st = sb + SM_STAGE0 + ps * STAGE_BYTES;
            mbar_expect_tx(sb + ps * 8, STAGE_BYTES);
            bulk_g2s(st,              Atiles + (size_t)(i + 2) * TILE_ELEMS, TILE_BYTES, sb + ps * 8);
            bulk_g2s(st + TILE_BYTES, Btiles + (size_t)(i + 2) * TILE_ELEMS, TILE_BYTES, sb + ps * 8);
        }

        const uint32_t stA = sb + SM_STAGE0 + stage * STAGE_BYTES;
        const uint32_t stB = stA + TILE_BYTES;
        const uint32_t csel = ((lane >> 4) << 4);

        // four k-slices of 16 within the 64-wide chunk (rows are 128B)
#pragma unroll
        for (int ks = 0; ks < 4; ++ks) {
            uint32_t ah[4][4];
#pragma unroll
            for (int t = 0; t < 4; ++t) {
                const uint32_t off = (uint32_t)(wm + (lane & 15) + t * 16) * 128 + ks * 32 + csel;
                ldx4(ah[t], stA + swz(off));
            }
            uint32_t bh[8][2];
#pragma unroll
            for (int p = 0; p < 4; ++p) {
                const uint32_t off = (uint32_t)(wn + (lane & 15) + p * 16) * 128 + ks * 32 + csel;
                uint32_t r[4];
                ldx4(r, stB + swz(off));
                bh[2*p][0] = r[0]; bh[2*p][1] = r[2];
                bh[2*p+1][0] = r[1]; bh[2*p+1][1] = r[3];
            }
#pragma unroll
            for (int mt = 0; mt < 4; ++mt)
#pragma unroll
                for (int nt = 0; nt < 8; ++nt)
                    mma16816(acc[mt][nt], ah[mt], bh[nt]);
        }

        ++stage; if (stage >= NSTAGE) { stage = 0; phase ^= 1; }
    }

    // epilogue (plain row-major C)
#pragma unroll
    for (int mt = 0; mt < 4; ++mt) {
        const int m = row0 + wm + mt * 16 + (lane >> 2);
#pragma unroll
        for (int nt = 0; nt < 8; ++nt) {
            const int n = col0 + wn + nt * 8 + (lane & 3) * 2;
            if (sizeof(OutT) == 2) {
                *(__half2*)((__half*)C + (size_t)m * EMB + n) =
                    __floats2half2_rn(acc[mt][nt][0], acc[mt][nt][1]);
                *(__half2*)((__half*)C + (size_t)(m + 8) * EMB + n) =
                    __floats2half2_rn(acc[mt][nt][2], acc[mt][nt][3]);
            } else {
                *(float2*)((float*)C + (size_t)m * EMB + n) =
                    make_float2(acc[mt][nt][0], acc[mt][nt][1]);
                *(float2*)((float*)C + (size_t)(m + 8) * EMB + n) =
                    make_float2(acc[mt][nt][2], acc[mt][nt][3]);
            }
        }
    }
}

// ---------------------------------------------------------------------------
// fp32 plain -> fp16 tiled+swizzled convert. 16 elems/thread, MLP=4.
// ---------------------------------------------------------------------------
__global__ __launch_bounds__(256)
void cvt_tiled_kernel(const float* __restrict__ src, __half* __restrict__ dst, int n)
{
    const int i = (blockIdx.x * 256 + threadIdx.x) * 16;
    if (i >= n) return;
    const int m = i >> 10;            // KDIM = 1024
    const int k = i & 1023;           // multiple of 16 -> all 16 in same 64-chunk

    float4 f[4];
#pragma unroll
    for (int c = 0; c < 4; ++c) f[c] = *(const float4*)(src + i + c * 4);

    const uint32_t tile = (uint32_t)(m >> 7) * KTILES + (k >> 6);
    char* tb = (char*)dst + (size_t)tile * TILE_BYTES;
    const uint32_t rowb = (uint32_t)(m & 127) << 7;
#pragma unroll
    for (int c = 0; c < 4; ++c) {
        __half h[4] = { __float2half_rn(f[c].x), __float2half_rn(f[c].y),
                        __float2half_rn(f[c].z), __float2half_rn(f[c].w) };
        const uint32_t o = swz(rowb | (((uint32_t)(k & 63) + c * 4) << 1));
        *(uint2*)(tb + o) = *(uint2*)h;
    }
}

// ---------------------------------------------------------------------------
// attention: banded Gaussian conv + constant heads (plain fp16 v -> tiled att)
// 2 columns x 8 queries per thread; half2 stores.
// ---------------------------------------------------------------------------
__global__ void attn_const_kernel(const __half* __restrict__ v, float* __restrict__ cst)
{
    const int b = blockIdx.x, which = blockIdx.y, p = threadIdx.x;
    const int h = which ? 4 : 3;
    float Z = 0.f, acc = 0.f;
#pragma unroll
    for (int j = 0; j < 8; ++j) {
        const int   k = which ? (L_SEQ - 1 - j) : j;
        const float w = c_wtab[j];
        Z += w;
        acc += w * __half2float(v[((size_t)b * L_SEQ + k) * EMB + h * 128 + p]);
    }
    cst[(b * 2 + which) * 128 + p] = acc / Z;
}

#define QT 16
#define CT 256
#define KT 32

__global__ __launch_bounds__(256)
void attn_kernel(const __half* __restrict__ v, __half* __restrict__ att,
                 const float* __restrict__ cst)
{
    const int b = blockIdx.z, q0 = blockIdx.y * QT, c0 = blockIdx.x * CT;
    const int tid = threadIdx.x;
    __shared__ float vt[KT][CT];

    const __half* vb = v + (size_t)b * L_SEQ * EMB;
#pragma unroll
    for (int i = 0; i < 8; ++i) {
        const int id = tid + i * 256;
        const int kb = id >> 6, cc = (id & 63) << 2;
        const int k  = q0 - 8 + kb;
        float4 val = make_float4(0.f, 0.f, 0.f, 0.f);
        if (k >= 0 && k < L_SEQ) {
            uint2 raw = *(const uint2*)(vb + (size_t)k * EMB + c0 + cc);
            const __half* hp = (const __half*)&raw;
            val = make_float4(__half2float(hp[0]), __half2float(hp[1]),
                              __half2float(hp[2]), __half2float(hp[3]));
        }
        *(float4*)&vt[kb][cc] = val;
    }
    __syncthreads();

    const int cp = tid & 127;          // column pair index
    const int qh = tid >> 7;           // query half: 0 or 1
    const int c  = c0 + cp * 2;        // even column
    const int h = c >> 7, pos = c_pos[h];

    const int mbase = b * L_SEQ + q0;
    const uint32_t tile = (uint32_t)(mbase >> 7) * KTILES + (c >> 6);
    char* tbase = (char*)att + (size_t)tile * TILE_BYTES;
    const uint32_t cbits = (uint32_t)(c & 63) << 1;
    const int qlo = qh * 8;

    if (pos <= 2) {
        const int off = (pos == 0) ? 0 : (pos == 1 ? -1 : 1);
#pragma unroll
        for (int qq = qlo; qq < qlo + 8; ++qq) {
            const int cen = q0 + qq + off;
            const int k0 = max(0, cen - 7), k1 = min(L_SEQ - 1, cen + 7);
            float Z = 0.f, a0 = 0.f, a1 = 0.f;
            for (int k = k0; k <= k1; ++k) {
                const int   d = k - cen;
                const float w = c_wtab[d < 0 ? -d : d];
                Z  += w;
                a0 += w * vt[k - q0 + 8][cp * 2];
                a1 += w * vt[k - q0 + 8][cp * 2 + 1];
            }
            const float inv = 1.f / Z;
            const uint32_t o = swz((((uint32_t)((mbase + qq) & 127)) << 7) | cbits);
            *(__half2*)(tbase + o) = __floats2half2_rn(a0 * inv, a1 * inv);
        }
    } else {
        const float* cb = cst + (b * 2 + (pos == 4)) * 128;
        const __half2 hh = __floats2half2_rn(cb[c & 127], cb[(c + 1) & 127]);
#pragma unroll
        for (int qq = qlo; qq < qlo + 8; ++qq) {
            const uint32_t o = swz((((uint32_t)((mbase + qq) & 127)) << 7) | cbits);
            *(__half2*)(tbase + o) = hh;
        }
    }
}

// ---------------------------------------------------------------------------
extern "C" void kernel_launch(void* const* d_in, const int* in_sizes, int n_in,
                              void* d_out, int out_size)
{
    const float* x     = (const float*)d_in[0];
    const float* W_in  = (const float*)d_in[1];
    const float* W_out = (const float*)d_in[2];
    float* out = (float*)d_out;

    __half *xh, *wih, *woh, *att, *v;
    float *cst;
    cudaGetSymbolAddress((void**)&xh,  g_xh);
    cudaGetSymbolAddress((void**)&wih, g_wih);
    cudaGetSymbolAddress((void**)&woh, g_woh);
    cudaGetSymbolAddress((void**)&att, g_att);
    cudaGetSymbolAddress((void**)&v,   g_v);
    cudaGetSymbolAddress((void**)&cst, g_cst);

    static bool attr_done = false;
    if (!attr_done) {
        cudaFuncSetAttribute(gemm_f16<__half>, cudaFuncAttributeMaxDynamicSharedMemorySize, SMEM_BYTES);
        cudaFuncSetAttribute(gemm_f16<float>,  cudaFuncAttributeMaxDynamicSharedMemorySize, SMEM_BYTES);
        attr_done = true;
    }

    const int NX = MTOT * KDIM, NW = EMB * KDIM;
    cvt_tiled_kernel<<<NX / (256 * 16), 256>>>(x, xh, NX);
    cvt_tiled_kernel<<<NW / (256 * 16), 256>>>(W_in,  wih, NW);
    cvt_tiled_kernel<<<NW / (256 * 16), 256>>>(W_out, woh, NW);

    const dim3 ggrid(EMB / BN, MTOT / BM);   // (8, 128)
    gemm_f16<__half><<<ggrid, GTHREADS, SMEM_BYTES>>>(xh, wih, v);

    attn_const_kernel<<<dim3(BATCH, 2), 128>>>(v, cst);
    attn_kernel<<<dim3(EMB / CT, L_SEQ / QT, BATCH), 256>>>(v, att, cst);

    gemm_f16<float><<<ggrid, GTHREADS, SMEM_BYTES>>>(att, woh, out);
}